// round 6
// baseline (speedup 1.0000x reference)
#include <cuda_runtime.h>
#include <cuda_fp16.h>
#include <math.h>

#define NN    50000
#define FIN   256
#define HHID  256
#define NH    4
#define HID   64
#define OUTC  64
#define NE    800000
#define NET   (NE + NN)
#define SLOPE 0.2f

// ---------------- device scratch ----------------
__device__ __half g_w1t[HHID * FIN];  // W1^T [N][K] fp16
__device__ __half g_w2t[OUTC * HHID]; // W2^T [N][K] fp16
__device__ __half g_h1h[NN * HHID];
__device__ __half g_heluh[NN * HHID];
__device__ __half g_h2h[NN * OUTC];
__device__ float g_as1[NN * NH];
__device__ float g_ad1[NN * NH];
__device__ float g_as2[NN];
__device__ float g_ad2[NN];
__device__ __align__(16) int g_deg[NN];
__device__ __align__(16) int g_cursor[NN];
__device__ __align__(16) int g_row[NN + 4];
__device__ int g_csr[NET];

// ---------------- helpers ----------------
__device__ __forceinline__ float warpSum(float v) {
    #pragma unroll
    for (int o = 16; o; o >>= 1) v += __shfl_xor_sync(0xFFFFFFFFu, v, o);
    return v;
}
__device__ __forceinline__ float warpMax(float v) {
    #pragma unroll
    for (int o = 16; o; o >>= 1) v = fmaxf(v, __shfl_xor_sync(0xFFFFFFFFu, v, o));
    return v;
}
__device__ __forceinline__ float lrelu(float a) { return a > 0.f ? a : SLOPE * a; }
__device__ __forceinline__ unsigned h2u(__half2 h) { return *(unsigned*)&h; }

// ---------------- weight conversion (transpose + fp16) ----------------
__global__ void cvtw_k(const float* __restrict__ W1, const float* __restrict__ W2) {
    int b = blockIdx.x;
    if (b < 16) {   // W1: 256x256 -> transpose
        int base = b * 4096 + threadIdx.x;
        #pragma unroll
        for (int it = 0; it < 16; it++) {
            int idx = base + it * 256;
            int k = idx >> 8, n = idx & 255;
            g_w1t[n * 256 + k] = __float2half(W1[idx]);
        }
    } else {        // W2: 256x64 -> transpose
        int base = (b - 16) * 4096 + threadIdx.x;
        #pragma unroll
        for (int it = 0; it < 16; it++) {
            int idx = base + it * 256;
            int k = idx >> 6, n = idx & 63;
            g_w2t[n * 256 + k] = __float2half(W2[idx]);
        }
    }
}

// ---------------- shared GEMM pieces ----------------
#define TBM 128
#define TBN 64
#define TBK 64
#define ASTH 72   // halves per A row (fp16 kernel)
#define ASTF 72   // floats per A row (fp32-A kernel)
#define BST 72    // halves per B row
#define GEMM_SMEM_H ((2 * TBM * ASTH + 2 * TBN * BST) * 2)
#define GEMM_SMEM_F (2 * TBM * ASTF * 4 + 2 * TBN * BST * 2)

__device__ __forceinline__ void cp16(unsigned dst, const void* src, int sz) {
    asm volatile("cp.async.cg.shared.global [%0], [%1], 16, %2;\n"
                 :: "r"(dst), "l"(src), "r"(sz));
}

#define MMA_H16(accv, a0, a1, a2, a3, b0, b1)                                    \
    asm volatile("mma.sync.aligned.m16n8k16.row.col.f32.f16.f16.f32 "            \
                 "{%0,%1,%2,%3}, {%4,%5,%6,%7}, {%8,%9}, {%0,%1,%2,%3};"         \
                 : "+f"(accv[0]), "+f"(accv[1]), "+f"(accv[2]), "+f"(accv[3])    \
                 : "r"(a0), "r"(a1), "r"(a2), "r"(a3), "r"(b0), "r"(b1))

// fused attention epilogue: C store + per-row dot with attS/attD (this CTA's 64 cols = 1 head)
__device__ __forceinline__ void gemm_epilogue(
        float acc[2][4][4], char* smem, __half* C,
        float* asOut, float* adOut, const float* attS, const float* attD,
        int asStr, int M, int Ncol,
        int bm0, int bn0, int bx, int wm, int wn, int g, int tg, int tid, int warpId) {
    #pragma unroll
    for (int mt = 0; mt < 2; mt++) {
        int r0 = bm0 + wm + mt * 16 + g;
        #pragma unroll
        for (int nt = 0; nt < 4; nt++) {
            int c = bn0 + wn + nt * 8 + tg * 2;
            if (r0 < M)
                *(__half2*)&C[(size_t)r0 * Ncol + c] =
                    __float22half2_rn(make_float2(acc[mt][nt][0], acc[mt][nt][1]));
            if (r0 + 8 < M)
                *(__half2*)&C[(size_t)(r0 + 8) * Ncol + c] =
                    __float22half2_rn(make_float2(acc[mt][nt][2], acc[mt][nt][3]));
        }
    }
    const float* aSp = attS + bx * 64;
    const float* aDp = attD + bx * 64;
    float pS[2][2] = {{0.f, 0.f}, {0.f, 0.f}};
    float pD[2][2] = {{0.f, 0.f}, {0.f, 0.f}};
    #pragma unroll
    for (int mt = 0; mt < 2; mt++)
        #pragma unroll
        for (int nt = 0; nt < 4; nt++) {
            int cIH = wn + nt * 8 + tg * 2;
            float s0 = aSp[cIH], s1 = aSp[cIH + 1];
            float d0 = aDp[cIH], d1 = aDp[cIH + 1];
            pS[mt][0] += acc[mt][nt][0] * s0 + acc[mt][nt][1] * s1;
            pS[mt][1] += acc[mt][nt][2] * s0 + acc[mt][nt][3] * s1;
            pD[mt][0] += acc[mt][nt][0] * d0 + acc[mt][nt][1] * d1;
            pD[mt][1] += acc[mt][nt][2] * d0 + acc[mt][nt][3] * d1;
        }
    #pragma unroll
    for (int o = 1; o <= 2; o <<= 1) {
        #pragma unroll
        for (int mt = 0; mt < 2; mt++)
            #pragma unroll
            for (int h = 0; h < 2; h++) {
                pS[mt][h] += __shfl_xor_sync(0xFFFFFFFFu, pS[mt][h], o);
                pD[mt][h] += __shfl_xor_sync(0xFFFFFFFFu, pD[mt][h], o);
            }
    }
    float* fbuf = (float*)smem;
    __syncthreads();
    if (tg == 0) {
        int warpN = warpId >> 2;
        #pragma unroll
        for (int mt = 0; mt < 2; mt++)
            #pragma unroll
            for (int h = 0; h < 2; h++) {
                int row = wm + mt * 16 + h * 8 + g;
                fbuf[(warpN * 128 + row) * 2 + 0] = pS[mt][h];
                fbuf[(warpN * 128 + row) * 2 + 1] = pD[mt][h];
            }
    }
    __syncthreads();
    if (tid < 128) {
        int gr = bm0 + tid;
        if (gr < M) {
            asOut[(size_t)gr * asStr + bx] = fbuf[tid * 2] + fbuf[(128 + tid) * 2];
            adOut[(size_t)gr * asStr + bx] = fbuf[tid * 2 + 1] + fbuf[(128 + tid) * 2 + 1];
        }
    }
}

// ---------------- GEMM1: A fp32 (x), inline fp16 conversion at fragment load ----------------
__global__ __launch_bounds__(256) void gemm_f32a_k(
        const float* __restrict__ A, const __half* __restrict__ Bt,
        __half* __restrict__ C,
        float* __restrict__ asOut, float* __restrict__ adOut,
        const float* __restrict__ attS, const float* __restrict__ attD,
        int asStr, int M, int Ncol, int K) {
    extern __shared__ char smem[];
    float*  As = (float*)smem;                                // [2][TBM][ASTF]
    __half* Bs = (__half*)(smem + 2 * TBM * ASTF * 4);        // [2][TBN][BST]
    const unsigned As_u = (unsigned)__cvta_generic_to_shared(As);
    const unsigned Bs_u = (unsigned)__cvta_generic_to_shared(Bs);

    const int tid = threadIdx.x;
    const int bm0 = blockIdx.y * TBM;
    const int bn0 = blockIdx.x * TBN;
    const int warpId = tid >> 5;
    const int lane = tid & 31;
    const int g  = lane >> 2;
    const int tg = lane & 3;
    const int wm = (warpId & 3) * 32;
    const int wn = (warpId >> 2) * 32;

    float acc[2][4][4];
    #pragma unroll
    for (int i = 0; i < 2; i++)
        #pragma unroll
        for (int j = 0; j < 4; j++)
            #pragma unroll
            for (int r = 0; r < 4; r++) acc[i][j][r] = 0.f;

    const int KT = K / TBK;

    auto loadTile = [&](int kt, int buf) {
        int k0 = kt * TBK;
        unsigned aBase = As_u + (unsigned)buf * TBM * ASTF * 4;
        unsigned bBase = Bs_u + (unsigned)buf * TBN * BST * 2;
        #pragma unroll
        for (int it = 0; it < 8; it++) {            // A fp32: 128 rows x 16 chunks
            int idx = tid + it * 256;
            int m = idx >> 4, ch = idx & 15;
            const float* src = A + (size_t)(bm0 + m) * K + k0 + ch * 4;
            int sz = (bm0 + m < M) ? 16 : 0;
            cp16(aBase + (unsigned)(m * ASTF + ch * 4) * 4, src, sz);
        }
        #pragma unroll
        for (int it = 0; it < 2; it++) {            // B fp16: 64 rows x 8 chunks
            int idx = tid + it * 256;
            int n = idx >> 3, ch = idx & 7;
            const __half* src = Bt + (size_t)(bn0 + n) * K + k0 + ch * 8;
            cp16(bBase + (unsigned)(n * BST + ch * 8) * 2, src, 16);
        }
        asm volatile("cp.async.commit_group;\n");
    };

    loadTile(0, 0);

    for (int kt = 0; kt < KT; kt++) {
        if (kt + 1 < KT) {
            loadTile(kt + 1, (kt + 1) & 1);
            asm volatile("cp.async.wait_group 1;\n");
        } else {
            asm volatile("cp.async.wait_group 0;\n");
        }
        __syncthreads();

        const float*  Ab = As + (kt & 1) * TBM * ASTF;
        const __half* Bb = Bs + (kt & 1) * TBN * BST;

        #pragma unroll
        for (int kc = 0; kc < TBK; kc += 16) {
            unsigned af[2][4], bf[4][2];
            #pragma unroll
            for (int mt = 0; mt < 2; mt++) {
                int r = wm + mt * 16 + g;
                float2 f0 = *(const float2*)&Ab[(r    ) * ASTF + kc + 2 * tg    ];
                float2 f1 = *(const float2*)&Ab[(r + 8) * ASTF + kc + 2 * tg    ];
                float2 f2 = *(const float2*)&Ab[(r    ) * ASTF + kc + 2 * tg + 8];
                float2 f3 = *(const float2*)&Ab[(r + 8) * ASTF + kc + 2 * tg + 8];
                af[mt][0] = h2u(__floats2half2_rn(f0.x, f0.y));
                af[mt][1] = h2u(__floats2half2_rn(f1.x, f1.y));
                af[mt][2] = h2u(__floats2half2_rn(f2.x, f2.y));
                af[mt][3] = h2u(__floats2half2_rn(f3.x, f3.y));
            }
            #pragma unroll
            for (int nt = 0; nt < 4; nt++) {
                int n = wn + nt * 8 + g;
                bf[nt][0] = *(const unsigned*)&Bb[n * BST + kc + 2 * tg    ];
                bf[nt][1] = *(const unsigned*)&Bb[n * BST + kc + 2 * tg + 8];
            }
            #pragma unroll
            for (int mt = 0; mt < 2; mt++)
                #pragma unroll
                for (int nt = 0; nt < 4; nt++)
                    MMA_H16(acc[mt][nt], af[mt][0], af[mt][1], af[mt][2], af[mt][3],
                            bf[nt][0], bf[nt][1]);
        }
        __syncthreads();
    }
    gemm_epilogue(acc, smem, C, asOut, adOut, attS, attD, asStr, M, Ncol,
                  bm0, bn0, blockIdx.x, wm, wn, g, tg, tid, warpId);
}

// ---------------- GEMM2: A fp16 ----------------
__global__ __launch_bounds__(256) void gemm_h16_k(
        const __half* __restrict__ A, const __half* __restrict__ Bt,
        __half* __restrict__ C,
        float* __restrict__ asOut, float* __restrict__ adOut,
        const float* __restrict__ attS, const float* __restrict__ attD,
        int asStr, int M, int Ncol, int K) {
    extern __shared__ char smem[];
    __half* As = (__half*)smem;
    __half* Bs = (__half*)smem + 2 * TBM * ASTH;
    const unsigned As_u = (unsigned)__cvta_generic_to_shared(As);
    const unsigned Bs_u = (unsigned)__cvta_generic_to_shared(Bs);

    const int tid = threadIdx.x;
    const int bm0 = blockIdx.y * TBM;
    const int bn0 = blockIdx.x * TBN;
    const int warpId = tid >> 5;
    const int lane = tid & 31;
    const int g  = lane >> 2;
    const int tg = lane & 3;
    const int wm = (warpId & 3) * 32;
    const int wn = (warpId >> 2) * 32;

    float acc[2][4][4];
    #pragma unroll
    for (int i = 0; i < 2; i++)
        #pragma unroll
        for (int j = 0; j < 4; j++)
            #pragma unroll
            for (int r = 0; r < 4; r++) acc[i][j][r] = 0.f;

    const int KT = K / TBK;

    auto loadTile = [&](int kt, int buf) {
        int k0 = kt * TBK;
        unsigned aBase = As_u + (unsigned)buf * TBM * ASTH * 2;
        unsigned bBase = Bs_u + (unsigned)buf * TBN * BST * 2;
        #pragma unroll
        for (int it = 0; it < 4; it++) {
            int idx = tid + it * 256;
            int m = idx >> 3, ch = idx & 7;
            const __half* src = A + (size_t)(bm0 + m) * K + k0 + ch * 8;
            int sz = (bm0 + m < M) ? 16 : 0;
            cp16(aBase + (unsigned)(m * ASTH + ch * 8) * 2, src, sz);
        }
        #pragma unroll
        for (int it = 0; it < 2; it++) {
            int idx = tid + it * 256;
            int n = idx >> 3, ch = idx & 7;
            const __half* src = Bt + (size_t)(bn0 + n) * K + k0 + ch * 8;
            cp16(bBase + (unsigned)(n * BST + ch * 8) * 2, src, 16);
        }
        asm volatile("cp.async.commit_group;\n");
    };

    loadTile(0, 0);

    for (int kt = 0; kt < KT; kt++) {
        if (kt + 1 < KT) {
            loadTile(kt + 1, (kt + 1) & 1);
            asm volatile("cp.async.wait_group 1;\n");
        } else {
            asm volatile("cp.async.wait_group 0;\n");
        }
        __syncthreads();

        const __half* Ab = As + (kt & 1) * TBM * ASTH;
        const __half* Bb = Bs + (kt & 1) * TBN * BST;

        #pragma unroll
        for (int kc = 0; kc < TBK; kc += 16) {
            unsigned af[2][4], bf[4][2];
            #pragma unroll
            for (int mt = 0; mt < 2; mt++) {
                int r = wm + mt * 16 + g;
                af[mt][0] = *(const unsigned*)&Ab[(r    ) * ASTH + kc + 2 * tg    ];
                af[mt][1] = *(const unsigned*)&Ab[(r + 8) * ASTH + kc + 2 * tg    ];
                af[mt][2] = *(const unsigned*)&Ab[(r    ) * ASTH + kc + 2 * tg + 8];
                af[mt][3] = *(const unsigned*)&Ab[(r + 8) * ASTH + kc + 2 * tg + 8];
            }
            #pragma unroll
            for (int nt = 0; nt < 4; nt++) {
                int n = wn + nt * 8 + g;
                bf[nt][0] = *(const unsigned*)&Bb[n * BST + kc + 2 * tg    ];
                bf[nt][1] = *(const unsigned*)&Bb[n * BST + kc + 2 * tg + 8];
            }
            #pragma unroll
            for (int mt = 0; mt < 2; mt++)
                #pragma unroll
                for (int nt = 0; nt < 4; nt++)
                    MMA_H16(acc[mt][nt], af[mt][0], af[mt][1], af[mt][2], af[mt][3],
                            bf[nt][0], bf[nt][1]);
        }
        __syncthreads();
    }
    gemm_epilogue(acc, smem, C, asOut, adOut, attS, attD, asStr, M, Ncol,
                  bm0, bn0, blockIdx.x, wm, wn, g, tg, tid, warpId);
}

// ---------------- CSR build ----------------
__global__ void count_k(const int* __restrict__ adj) {
    int e = blockIdx.x * blockDim.x + threadIdx.x;
    if (e >= NET) return;
    int d = (e < NE) ? adj[NE + e] : (e - NE);
    atomicAdd(&g_deg[d], 1);
}

// single-block full exclusive scan; also writes cursor = row
__global__ __launch_bounds__(1024) void scanfull_k() {
    __shared__ int wsum[32];
    __shared__ int wscan[32];
    __shared__ int blktot;
    int tid = threadIdx.x, lane = tid & 31, wid = tid >> 5;
    int carry = 0;
    for (int base = 0; base < NN; base += 4096) {
        int idx = base + tid * 4;
        int4 v = make_int4(0, 0, 0, 0);
        if (idx < NN) v = *(const int4*)&g_deg[idx];
        int p1 = v.x + v.y, p2 = p1 + v.z, p3 = p2 + v.w;
        int inc = p3;
        #pragma unroll
        for (int o = 1; o < 32; o <<= 1) {
            int t = __shfl_up_sync(0xFFFFFFFFu, inc, o);
            if (lane >= o) inc += t;
        }
        if (lane == 31) wsum[wid] = inc;
        __syncthreads();
        if (wid == 0) {
            int x = wsum[lane];
            int xs = x;
            #pragma unroll
            for (int o = 1; o < 32; o <<= 1) {
                int t = __shfl_up_sync(0xFFFFFFFFu, xs, o);
                if (lane >= o) xs += t;
            }
            wscan[lane] = xs - x;
            if (lane == 31) blktot = xs;
        }
        __syncthreads();
        int excl = carry + wscan[wid] + (inc - p3);
        if (idx < NN) {
            int4 r = make_int4(excl, excl + v.x, excl + p1, excl + p2);
            *(int4*)&g_row[idx] = r;
            *(int4*)&g_cursor[idx] = r;
        }
        carry += blktot;
        __syncthreads();
    }
    if (tid == 0) g_row[NN] = NET;
}

__global__ void scatter_k(const int* __restrict__ adj) {
    int e = blockIdx.x * blockDim.x + threadIdx.x;
    if (e >= NET) return;
    int s, d;
    if (e < NE) { s = adj[e]; d = adj[NE + e]; }
    else        { s = e - NE; d = s; }
    int pos = atomicAdd(&g_cursor[d], 1);
    g_csr[pos] = s;
}

// ---------------- layer-1 softmax-aggregate + bias + ELU (warp per dst, MLP-4) ----------------
__global__ void agg1_k(const float* __restrict__ b1) {
    int n = (blockIdx.x * blockDim.x + threadIdx.x) >> 5;
    int lane = threadIdx.x & 31;
    if (n >= NN) return;
    int beg = g_row[n], end = g_row[n + 1];
    float4 adv = *(const float4*)&g_ad1[n * 4];

    float m[4] = {-1e30f, -1e30f, -1e30f, -1e30f};
    float s[4] = {0.f, 0.f, 0.f, 0.f};
    for (int e = beg + lane; e < end; e += 32) {
        int src = g_csr[e];
        float4 asv = *(const float4*)&g_as1[src * 4];
        float a[4] = {lrelu(asv.x + adv.x), lrelu(asv.y + adv.y),
                      lrelu(asv.z + adv.z), lrelu(asv.w + adv.w)};
        #pragma unroll
        for (int h = 0; h < 4; h++) {
            float mn = fmaxf(m[h], a[h]);
            s[h] = s[h] * expf(m[h] - mn) + expf(a[h] - mn);
            m[h] = mn;
        }
    }
    #pragma unroll
    for (int h = 0; h < 4; h++) {
        #pragma unroll
        for (int o = 16; o; o >>= 1) {
            float om = __shfl_xor_sync(0xFFFFFFFFu, m[h], o);
            float os = __shfl_xor_sync(0xFFFFFFFFu, s[h], o);
            float mn = fmaxf(m[h], om);
            s[h] = s[h] * expf(m[h] - mn) + os * expf(om - mn);
            m[h] = mn;
        }
    }

    int hh = lane >> 3;
    float myM = m[0], myS = s[0];
    if (hh == 1) { myM = m[1]; myS = s[1]; }
    else if (hh == 2) { myM = m[2]; myS = s[2]; }
    else if (hh == 3) { myM = m[3]; myS = s[3]; }
    float myInv = 1.f / myS;
    float myAd  = (hh == 0) ? adv.x : (hh == 1) ? adv.y : (hh == 2) ? adv.z : adv.w;

    float a0 = 0.f, a1 = 0.f, a2 = 0.f, a3 = 0.f, a4 = 0.f, a5 = 0.f, a6 = 0.f, a7 = 0.f;
    const uint4* h1p = (const uint4*)g_h1h;
    int e = beg;
    // MLP-4 pipelined main loop
    for (; e + 4 <= end; e += 4) {
        int s0 = g_csr[e], s1 = g_csr[e + 1], s2 = g_csr[e + 2], s3 = g_csr[e + 3];
        float w0 = lrelu(g_as1[s0 * 4 + hh] + myAd);
        float w1 = lrelu(g_as1[s1 * 4 + hh] + myAd);
        float w2 = lrelu(g_as1[s2 * 4 + hh] + myAd);
        float w3 = lrelu(g_as1[s3 * 4 + hh] + myAd);
        uint4 r0 = h1p[(size_t)s0 * 32 + lane];
        uint4 r1 = h1p[(size_t)s1 * 32 + lane];
        uint4 r2 = h1p[(size_t)s2 * 32 + lane];
        uint4 r3 = h1p[(size_t)s3 * 32 + lane];
        w0 = expf(w0 - myM) * myInv;
        w1 = expf(w1 - myM) * myInv;
        w2 = expf(w2 - myM) * myInv;
        w3 = expf(w3 - myM) * myInv;
        #pragma unroll
        for (int q = 0; q < 4; q++) {
            uint4 rr = (q == 0) ? r0 : (q == 1) ? r1 : (q == 2) ? r2 : r3;
            float ww = (q == 0) ? w0 : (q == 1) ? w1 : (q == 2) ? w2 : w3;
            float2 p0 = __half22float2(*(__half2*)&rr.x);
            float2 p1 = __half22float2(*(__half2*)&rr.y);
            float2 p2 = __half22float2(*(__half2*)&rr.z);
            float2 p3 = __half22float2(*(__half2*)&rr.w);
            a0 += ww * p0.x; a1 += ww * p0.y; a2 += ww * p1.x; a3 += ww * p1.y;
            a4 += ww * p2.x; a5 += ww * p2.y; a6 += ww * p3.x; a7 += ww * p3.y;
        }
    }
    for (; e < end; e++) {
        int src = g_csr[e];
        float w = expf(lrelu(g_as1[src * 4 + hh] + myAd) - myM) * myInv;
        uint4 raw = h1p[(size_t)src * 32 + lane];
        float2 p0 = __half22float2(*(__half2*)&raw.x);
        float2 p1 = __half22float2(*(__half2*)&raw.y);
        float2 p2 = __half22float2(*(__half2*)&raw.z);
        float2 p3 = __half22float2(*(__half2*)&raw.w);
        a0 += w * p0.x; a1 += w * p0.y; a2 += w * p1.x; a3 += w * p1.y;
        a4 += w * p2.x; a5 += w * p2.y; a6 += w * p3.x; a7 += w * p3.y;
    }
    int c0 = lane * 8;
    float4 bb0 = *(const float4*)&b1[c0];
    float4 bb1 = *(const float4*)&b1[c0 + 4];
    float o[8] = {a0 + bb0.x, a1 + bb0.y, a2 + bb0.z, a3 + bb0.w,
                  a4 + bb1.x, a5 + bb1.y, a6 + bb1.z, a7 + bb1.w};
    #pragma unroll
    for (int j = 0; j < 8; j++) o[j] = (o[j] > 0.f) ? o[j] : expm1f(o[j]);
    uint4 packed;
    *(__half2*)&packed.x = __float22half2_rn(make_float2(o[0], o[1]));
    *(__half2*)&packed.y = __float22half2_rn(make_float2(o[2], o[3]));
    *(__half2*)&packed.z = __float22half2_rn(make_float2(o[4], o[5]));
    *(__half2*)&packed.w = __float22half2_rn(make_float2(o[6], o[7]));
    *(uint4*)&g_heluh[(size_t)n * HHID + c0] = packed;
}

// ---------------- layer-2 softmax-aggregate + bias + log_softmax (MLP-4) ----------------
__global__ void agg2_k(const float* __restrict__ b2, float* __restrict__ out) {
    int n = (blockIdx.x * blockDim.x + threadIdx.x) >> 5;
    int lane = threadIdx.x & 31;
    if (n >= NN) return;
    int beg = g_row[n], end = g_row[n + 1];
    float adv = g_ad2[n];

    float m = -1e30f, ss = 0.f;
    for (int e = beg + lane; e < end; e += 32) {
        float a = lrelu(g_as2[g_csr[e]] + adv);
        float mn = fmaxf(m, a);
        ss = ss * expf(m - mn) + expf(a - mn);
        m = mn;
    }
    #pragma unroll
    for (int o = 16; o; o >>= 1) {
        float om = __shfl_xor_sync(0xFFFFFFFFu, m, o);
        float os = __shfl_xor_sync(0xFFFFFFFFu, ss, o);
        float mn = fmaxf(m, om);
        ss = ss * expf(m - mn) + os * expf(om - mn);
        m = mn;
    }
    float inv = 1.f / ss;

    float acc0 = 0.f, acc1 = 0.f;
    const __half2* h2p = (const __half2*)g_h2h;
    int e = beg;
    for (; e + 4 <= end; e += 4) {
        int s0 = g_csr[e], s1 = g_csr[e + 1], s2 = g_csr[e + 2], s3 = g_csr[e + 3];
        float w0 = lrelu(g_as2[s0] + adv);
        float w1 = lrelu(g_as2[s1] + adv);
        float w2 = lrelu(g_as2[s2] + adv);
        float w3 = lrelu(g_as2[s3] + adv);
        float2 v0 = __half22float2(h2p[(size_t)s0 * 32 + lane]);
        float2 v1 = __half22float2(h2p[(size_t)s1 * 32 + lane]);
        float2 v2 = __half22float2(h2p[(size_t)s2 * 32 + lane]);
        float2 v3 = __half22float2(h2p[(size_t)s3 * 32 + lane]);
        w0 = expf(w0 - m) * inv; w1 = expf(w1 - m) * inv;
        w2 = expf(w2 - m) * inv; w3 = expf(w3 - m) * inv;
        acc0 += w0 * v0.x + w1 * v1.x + w2 * v2.x + w3 * v3.x;
        acc1 += w0 * v0.y + w1 * v1.y + w2 * v2.y + w3 * v3.y;
    }
    for (; e < end; e++) {
        int src = g_csr[e];
        float w = expf(lrelu(g_as2[src] + adv) - m) * inv;
        float2 v = __half22float2(h2p[(size_t)src * 32 + lane]);
        acc0 += w * v.x; acc1 += w * v.y;
    }
    acc0 += b2[lane * 2]; acc1 += b2[lane * 2 + 1];

    float M = warpMax(fmaxf(acc0, acc1));
    float S = warpSum(expf(acc0 - M) + expf(acc1 - M));
    float L = M + logf(S);
    out[(size_t)n * OUTC + lane * 2]     = acc0 - L;
    out[(size_t)n * OUTC + lane * 2 + 1] = acc1 - L;
}

// ---------------- launch ----------------
extern "C" void kernel_launch(void* const* d_in, const int* in_sizes, int n_in,
                              void* d_out, int out_size) {
    const float* x        = (const float*)d_in[0];
    const int*   adj      = (const int*)d_in[1];
    const float* W1       = (const float*)d_in[2];
    const float* att_src1 = (const float*)d_in[3];
    const float* att_dst1 = (const float*)d_in[4];
    const float* b1       = (const float*)d_in[5];
    const float* W2       = (const float*)d_in[6];
    const float* att_src2 = (const float*)d_in[7];
    const float* att_dst2 = (const float*)d_in[8];
    const float* b2       = (const float*)d_in[9];
    float* out = (float*)d_out;

    __half *p_w1t, *p_w2t, *p_h1h, *p_heluh, *p_h2h;
    float *p_as1, *p_ad1, *p_as2, *p_ad2;
    int *p_deg;
    cudaGetSymbolAddress((void**)&p_w1t, g_w1t);
    cudaGetSymbolAddress((void**)&p_w2t, g_w2t);
    cudaGetSymbolAddress((void**)&p_h1h, g_h1h);
    cudaGetSymbolAddress((void**)&p_heluh, g_heluh);
    cudaGetSymbolAddress((void**)&p_h2h, g_h2h);
    cudaGetSymbolAddress((void**)&p_as1, g_as1);
    cudaGetSymbolAddress((void**)&p_ad1, g_ad1);
    cudaGetSymbolAddress((void**)&p_as2, g_as2);
    cudaGetSymbolAddress((void**)&p_ad2, g_ad2);
    cudaGetSymbolAddress((void**)&p_deg, g_deg);

    static bool attrSet = false;
    if (!attrSet) {
        cudaFuncSetAttribute(gemm_f32a_k, cudaFuncAttributeMaxDynamicSharedMemorySize, GEMM_SMEM_F);
        cudaFuncSetAttribute(gemm_h16_k, cudaFuncAttributeMaxDynamicSharedMemorySize, GEMM_SMEM_H);
        attrSet = true;
    }

    const int nodeBlocks = (NN * 32 + 255) / 256;
    const int edgeBlocks = (NET + 255) / 256;

    cvtw_k<<<20, 256>>>(W1, W2);                                        // 1
    cudaMemsetAsync(p_deg, 0, NN * sizeof(int));                        // (memset node)
    count_k<<<edgeBlocks, 256>>>(adj);                                  // 2
    gemm_f32a_k<<<dim3(HHID / TBN, (NN + TBM - 1) / TBM), 256, GEMM_SMEM_F>>>(  // 3/4
        x, p_w1t, p_h1h, p_as1, p_ad1, att_src1, att_dst1, NH, NN, HHID, FIN);
    scanfull_k<<<1, 1024>>>();                                          // 4/5
    scatter_k<<<edgeBlocks, 256>>>(adj);                                // 5/6
    agg1_k<<<nodeBlocks, 256>>>(b1);                                    // 6/7
    gemm_h16_k<<<dim3(OUTC / TBN, (NN + TBM - 1) / TBM), 256, GEMM_SMEM_H>>>(   // 7/8
        p_heluh, p_w2t, p_h2h, p_as2, p_ad2, att_src2, att_dst2, 1, NN, OUTC, HHID);
    agg2_k<<<nodeBlocks, 256>>>(b2, out);                               // 8/9
}

// round 7
// speedup vs baseline: 1.0860x; 1.0860x over previous
#include <cuda_runtime.h>
#include <cuda_fp16.h>
#include <math.h>

#define NN    50000
#define FIN   256
#define HHID  256
#define NH    4
#define HID   64
#define OUTC  64
#define NE    800000
#define NET   (NE + NN)
#define SLOPE 0.2f

// ---------------- device scratch ----------------
__device__ __half g_w1t[HHID * FIN];  // W1^T [N][K] fp16
__device__ __half g_w2t[OUTC * HHID]; // W2^T [N][K] fp16
__device__ __half g_h1h[NN * HHID];
__device__ __half g_heluh[NN * HHID];
__device__ __half g_h2h[NN * OUTC];
__device__ float g_as1[NN * NH];
__device__ float g_ad1[NN * NH];
__device__ float g_as2[NN];
__device__ float g_ad2[NN];
__device__ __align__(16) int g_deg[NN];
__device__ __align__(16) int g_cursor[NN];
__device__ __align__(16) int g_row[NN + 4];
__device__ int g_csr[NET];
__device__ int g_bsums[128];

// ---------------- helpers ----------------
__device__ __forceinline__ float warpSum(float v) {
    #pragma unroll
    for (int o = 16; o; o >>= 1) v += __shfl_xor_sync(0xFFFFFFFFu, v, o);
    return v;
}
__device__ __forceinline__ float warpMax(float v) {
    #pragma unroll
    for (int o = 16; o; o >>= 1) v = fmaxf(v, __shfl_xor_sync(0xFFFFFFFFu, v, o));
    return v;
}
__device__ __forceinline__ float lrelu(float a) { return a > 0.f ? a : SLOPE * a; }
__device__ __forceinline__ unsigned h2u(__half2 h) { return *(unsigned*)&h; }

// ---------------- weight conversion (transpose + fp16) ----------------
__global__ void cvtw_k(const float* __restrict__ W1, const float* __restrict__ W2) {
    int b = blockIdx.x;
    if (b < 16) {
        int base = b * 4096 + threadIdx.x;
        #pragma unroll
        for (int it = 0; it < 16; it++) {
            int idx = base + it * 256;
            int k = idx >> 8, n = idx & 255;
            g_w1t[n * 256 + k] = __float2half(W1[idx]);
        }
    } else {
        int base = (b - 16) * 4096 + threadIdx.x;
        #pragma unroll
        for (int it = 0; it < 16; it++) {
            int idx = base + it * 256;
            int k = idx >> 6, n = idx & 63;
            g_w2t[n * 256 + k] = __float2half(W2[idx]);
        }
    }
}

// ---------------- shared GEMM pieces ----------------
#define TBM 128
#define TBN 64
#define TBK 64
#define ASTH 72
#define ASTF 72
#define BST 72
#define GEMM_SMEM_H ((2 * TBM * ASTH + 2 * TBN * BST) * 2)
#define GEMM_SMEM_F (2 * TBM * ASTF * 4 + 2 * TBN * BST * 2)

__device__ __forceinline__ void cp16(unsigned dst, const void* src, int sz) {
    asm volatile("cp.async.cg.shared.global [%0], [%1], 16, %2;\n"
                 :: "r"(dst), "l"(src), "r"(sz));
}

#define MMA_H16(accv, a0, a1, a2, a3, b0, b1)                                    \
    asm volatile("mma.sync.aligned.m16n8k16.row.col.f32.f16.f16.f32 "            \
                 "{%0,%1,%2,%3}, {%4,%5,%6,%7}, {%8,%9}, {%0,%1,%2,%3};"         \
                 : "+f"(accv[0]), "+f"(accv[1]), "+f"(accv[2]), "+f"(accv[3])    \
                 : "r"(a0), "r"(a1), "r"(a2), "r"(a3), "r"(b0), "r"(b1))

__device__ __forceinline__ void gemm_epilogue(
        float acc[2][4][4], char* smem, __half* C,
        float* asOut, float* adOut, const float* attS, const float* attD,
        int asStr, int M, int Ncol,
        int bm0, int bn0, int bx, int wm, int wn, int g, int tg, int tid, int warpId) {
    #pragma unroll
    for (int mt = 0; mt < 2; mt++) {
        int r0 = bm0 + wm + mt * 16 + g;
        #pragma unroll
        for (int nt = 0; nt < 4; nt++) {
            int c = bn0 + wn + nt * 8 + tg * 2;
            if (r0 < M)
                *(__half2*)&C[(size_t)r0 * Ncol + c] =
                    __float22half2_rn(make_float2(acc[mt][nt][0], acc[mt][nt][1]));
            if (r0 + 8 < M)
                *(__half2*)&C[(size_t)(r0 + 8) * Ncol + c] =
                    __float22half2_rn(make_float2(acc[mt][nt][2], acc[mt][nt][3]));
        }
    }
    const float* aSp = attS + bx * 64;
    const float* aDp = attD + bx * 64;
    float pS[2][2] = {{0.f, 0.f}, {0.f, 0.f}};
    float pD[2][2] = {{0.f, 0.f}, {0.f, 0.f}};
    #pragma unroll
    for (int mt = 0; mt < 2; mt++)
        #pragma unroll
        for (int nt = 0; nt < 4; nt++) {
            int cIH = wn + nt * 8 + tg * 2;
            float s0 = aSp[cIH], s1 = aSp[cIH + 1];
            float d0 = aDp[cIH], d1 = aDp[cIH + 1];
            pS[mt][0] += acc[mt][nt][0] * s0 + acc[mt][nt][1] * s1;
            pS[mt][1] += acc[mt][nt][2] * s0 + acc[mt][nt][3] * s1;
            pD[mt][0] += acc[mt][nt][0] * d0 + acc[mt][nt][1] * d1;
            pD[mt][1] += acc[mt][nt][2] * d0 + acc[mt][nt][3] * d1;
        }
    #pragma unroll
    for (int o = 1; o <= 2; o <<= 1) {
        #pragma unroll
        for (int mt = 0; mt < 2; mt++)
            #pragma unroll
            for (int h = 0; h < 2; h++) {
                pS[mt][h] += __shfl_xor_sync(0xFFFFFFFFu, pS[mt][h], o);
                pD[mt][h] += __shfl_xor_sync(0xFFFFFFFFu, pD[mt][h], o);
            }
    }
    float* fbuf = (float*)smem;
    __syncthreads();
    if (tg == 0) {
        int warpN = warpId >> 2;
        #pragma unroll
        for (int mt = 0; mt < 2; mt++)
            #pragma unroll
            for (int h = 0; h < 2; h++) {
                int row = wm + mt * 16 + h * 8 + g;
                fbuf[(warpN * 128 + row) * 2 + 0] = pS[mt][h];
                fbuf[(warpN * 128 + row) * 2 + 1] = pD[mt][h];
            }
    }
    __syncthreads();
    if (tid < 128) {
        int gr = bm0 + tid;
        if (gr < M) {
            asOut[(size_t)gr * asStr + bx] = fbuf[tid * 2] + fbuf[(128 + tid) * 2];
            adOut[(size_t)gr * asStr + bx] = fbuf[tid * 2 + 1] + fbuf[(128 + tid) * 2 + 1];
        }
    }
}

// ---------------- GEMM1: A fp32, inline fp16 conversion ----------------
__global__ __launch_bounds__(256) void gemm_f32a_k(
        const float* __restrict__ A, const __half* __restrict__ Bt,
        __half* __restrict__ C,
        float* __restrict__ asOut, float* __restrict__ adOut,
        const float* __restrict__ attS, const float* __restrict__ attD,
        int asStr, int M, int Ncol, int K) {
    extern __shared__ char smem[];
    float*  As = (float*)smem;
    __half* Bs = (__half*)(smem + 2 * TBM * ASTF * 4);
    const unsigned As_u = (unsigned)__cvta_generic_to_shared(As);
    const unsigned Bs_u = (unsigned)__cvta_generic_to_shared(Bs);

    const int tid = threadIdx.x;
    const int bm0 = blockIdx.y * TBM;
    const int bn0 = blockIdx.x * TBN;
    const int warpId = tid >> 5;
    const int lane = tid & 31;
    const int g  = lane >> 2;
    const int tg = lane & 3;
    const int wm = (warpId & 3) * 32;
    const int wn = (warpId >> 2) * 32;

    float acc[2][4][4];
    #pragma unroll
    for (int i = 0; i < 2; i++)
        #pragma unroll
        for (int j = 0; j < 4; j++)
            #pragma unroll
            for (int r = 0; r < 4; r++) acc[i][j][r] = 0.f;

    const int KT = K / TBK;

    auto loadTile = [&](int kt, int buf) {
        int k0 = kt * TBK;
        unsigned aBase = As_u + (unsigned)buf * TBM * ASTF * 4;
        unsigned bBase = Bs_u + (unsigned)buf * TBN * BST * 2;
        #pragma unroll
        for (int it = 0; it < 8; it++) {
            int idx = tid + it * 256;
            int m = idx >> 4, ch = idx & 15;
            const float* src = A + (size_t)(bm0 + m) * K + k0 + ch * 4;
            int sz = (bm0 + m < M) ? 16 : 0;
            cp16(aBase + (unsigned)(m * ASTF + ch * 4) * 4, src, sz);
        }
        #pragma unroll
        for (int it = 0; it < 2; it++) {
            int idx = tid + it * 256;
            int n = idx >> 3, ch = idx & 7;
            const __half* src = Bt + (size_t)(bn0 + n) * K + k0 + ch * 8;
            cp16(bBase + (unsigned)(n * BST + ch * 8) * 2, src, 16);
        }
        asm volatile("cp.async.commit_group;\n");
    };

    loadTile(0, 0);

    for (int kt = 0; kt < KT; kt++) {
        if (kt + 1 < KT) {
            loadTile(kt + 1, (kt + 1) & 1);
            asm volatile("cp.async.wait_group 1;\n");
        } else {
            asm volatile("cp.async.wait_group 0;\n");
        }
        __syncthreads();

        const float*  Ab = As + (kt & 1) * TBM * ASTF;
        const __half* Bb = Bs + (kt & 1) * TBN * BST;

        #pragma unroll
        for (int kc = 0; kc < TBK; kc += 16) {
            unsigned af[2][4], bf[4][2];
            #pragma unroll
            for (int mt = 0; mt < 2; mt++) {
                int r = wm + mt * 16 + g;
                float2 f0 = *(const float2*)&Ab[(r    ) * ASTF + kc + 2 * tg    ];
                float2 f1 = *(const float2*)&Ab[(r + 8) * ASTF + kc + 2 * tg    ];
                float2 f2 = *(const float2*)&Ab[(r    ) * ASTF + kc + 2 * tg + 8];
                float2 f3 = *(const float2*)&Ab[(r + 8) * ASTF + kc + 2 * tg + 8];
                af[mt][0] = h2u(__floats2half2_rn(f0.x, f0.y));
                af[mt][1] = h2u(__floats2half2_rn(f1.x, f1.y));
                af[mt][2] = h2u(__floats2half2_rn(f2.x, f2.y));
                af[mt][3] = h2u(__floats2half2_rn(f3.x, f3.y));
            }
            #pragma unroll
            for (int nt = 0; nt < 4; nt++) {
                int n = wn + nt * 8 + g;
                bf[nt][0] = *(const unsigned*)&Bb[n * BST + kc + 2 * tg    ];
                bf[nt][1] = *(const unsigned*)&Bb[n * BST + kc + 2 * tg + 8];
            }
            #pragma unroll
            for (int mt = 0; mt < 2; mt++)
                #pragma unroll
                for (int nt = 0; nt < 4; nt++)
                    MMA_H16(acc[mt][nt], af[mt][0], af[mt][1], af[mt][2], af[mt][3],
                            bf[nt][0], bf[nt][1]);
        }
        __syncthreads();
    }
    gemm_epilogue(acc, smem, C, asOut, adOut, attS, attD, asStr, M, Ncol,
                  bm0, bn0, blockIdx.x, wm, wn, g, tg, tid, warpId);
}

// ---------------- GEMM2: A fp16 ----------------
__global__ __launch_bounds__(256) void gemm_h16_k(
        const __half* __restrict__ A, const __half* __restrict__ Bt,
        __half* __restrict__ C,
        float* __restrict__ asOut, float* __restrict__ adOut,
        const float* __restrict__ attS, const float* __restrict__ attD,
        int asStr, int M, int Ncol, int K) {
    extern __shared__ char smem[];
    __half* As = (__half*)smem;
    __half* Bs = (__half*)smem + 2 * TBM * ASTH;
    const unsigned As_u = (unsigned)__cvta_generic_to_shared(As);
    const unsigned Bs_u = (unsigned)__cvta_generic_to_shared(Bs);

    const int tid = threadIdx.x;
    const int bm0 = blockIdx.y * TBM;
    const int bn0 = blockIdx.x * TBN;
    const int warpId = tid >> 5;
    const int lane = tid & 31;
    const int g  = lane >> 2;
    const int tg = lane & 3;
    const int wm = (warpId & 3) * 32;
    const int wn = (warpId >> 2) * 32;

    float acc[2][4][4];
    #pragma unroll
    for (int i = 0; i < 2; i++)
        #pragma unroll
        for (int j = 0; j < 4; j++)
            #pragma unroll
            for (int r = 0; r < 4; r++) acc[i][j][r] = 0.f;

    const int KT = K / TBK;

    auto loadTile = [&](int kt, int buf) {
        int k0 = kt * TBK;
        unsigned aBase = As_u + (unsigned)buf * TBM * ASTH * 2;
        unsigned bBase = Bs_u + (unsigned)buf * TBN * BST * 2;
        #pragma unroll
        for (int it = 0; it < 4; it++) {
            int idx = tid + it * 256;
            int m = idx >> 3, ch = idx & 7;
            const __half* src = A + (size_t)(bm0 + m) * K + k0 + ch * 8;
            int sz = (bm0 + m < M) ? 16 : 0;
            cp16(aBase + (unsigned)(m * ASTH + ch * 8) * 2, src, sz);
        }
        #pragma unroll
        for (int it = 0; it < 2; it++) {
            int idx = tid + it * 256;
            int n = idx >> 3, ch = idx & 7;
            const __half* src = Bt + (size_t)(bn0 + n) * K + k0 + ch * 8;
            cp16(bBase + (unsigned)(n * BST + ch * 8) * 2, src, 16);
        }
        asm volatile("cp.async.commit_group;\n");
    };

    loadTile(0, 0);

    for (int kt = 0; kt < KT; kt++) {
        if (kt + 1 < KT) {
            loadTile(kt + 1, (kt + 1) & 1);
            asm volatile("cp.async.wait_group 1;\n");
        } else {
            asm volatile("cp.async.wait_group 0;\n");
        }
        __syncthreads();

        const __half* Ab = As + (kt & 1) * TBM * ASTH;
        const __half* Bb = Bs + (kt & 1) * TBN * BST;

        #pragma unroll
        for (int kc = 0; kc < TBK; kc += 16) {
            unsigned af[2][4], bf[4][2];
            #pragma unroll
            for (int mt = 0; mt < 2; mt++) {
                int r = wm + mt * 16 + g;
                af[mt][0] = *(const unsigned*)&Ab[(r    ) * ASTH + kc + 2 * tg    ];
                af[mt][1] = *(const unsigned*)&Ab[(r + 8) * ASTH + kc + 2 * tg    ];
                af[mt][2] = *(const unsigned*)&Ab[(r    ) * ASTH + kc + 2 * tg + 8];
                af[mt][3] = *(const unsigned*)&Ab[(r + 8) * ASTH + kc + 2 * tg + 8];
            }
            #pragma unroll
            for (int nt = 0; nt < 4; nt++) {
                int n = wn + nt * 8 + g;
                bf[nt][0] = *(const unsigned*)&Bb[n * BST + kc + 2 * tg    ];
                bf[nt][1] = *(const unsigned*)&Bb[n * BST + kc + 2 * tg + 8];
            }
            #pragma unroll
            for (int mt = 0; mt < 2; mt++)
                #pragma unroll
                for (int nt = 0; nt < 4; nt++)
                    MMA_H16(acc[mt][nt], af[mt][0], af[mt][1], af[mt][2], af[mt][3],
                            bf[nt][0], bf[nt][1]);
        }
        __syncthreads();
    }
    gemm_epilogue(acc, smem, C, asOut, adOut, attS, attD, asStr, M, Ncol,
                  bm0, bn0, blockIdx.x, wm, wn, g, tg, tid, warpId);
}

// ---------------- CSR build (3-kernel scan, cursor fused into scan3) ----------------
__global__ void count_k(const int* __restrict__ adj) {
    int e = blockIdx.x * blockDim.x + threadIdx.x;
    if (e >= NET) return;
    int d = (e < NE) ? adj[NE + e] : (e - NE);
    atomicAdd(&g_deg[d], 1);
}
__global__ void scan1_k(int n) {
    __shared__ int sh[512];
    int i = blockIdx.x * 512 + threadIdx.x;
    int v = (i < n) ? g_deg[i] : 0;
    sh[threadIdx.x] = v;
    __syncthreads();
    for (int off = 1; off < 512; off <<= 1) {
        int t = (threadIdx.x >= (unsigned)off) ? sh[threadIdx.x - off] : 0;
        __syncthreads();
        sh[threadIdx.x] += t;
        __syncthreads();
    }
    if (i < n) g_row[i] = sh[threadIdx.x] - v;
    if (threadIdx.x == 511) g_bsums[blockIdx.x] = sh[511];
}
__global__ void scan2_k(int nb) {
    __shared__ int sh[128];
    int v = (threadIdx.x < (unsigned)nb) ? g_bsums[threadIdx.x] : 0;
    sh[threadIdx.x] = v;
    __syncthreads();
    for (int off = 1; off < 128; off <<= 1) {
        int t = (threadIdx.x >= (unsigned)off) ? sh[threadIdx.x - off] : 0;
        __syncthreads();
        sh[threadIdx.x] += t;
        __syncthreads();
    }
    if (threadIdx.x < (unsigned)nb) g_bsums[threadIdx.x] = sh[threadIdx.x] - v;
}
__global__ void scan3_k(int n) {
    int i = blockIdx.x * 512 + threadIdx.x;
    if (i < n) {
        int r = g_row[i] + g_bsums[blockIdx.x];
        g_row[i] = r;
        g_cursor[i] = r;
    }
    if (i == 0) g_row[n] = NET;
}
__global__ void scatter_k(const int* __restrict__ adj) {
    int e = blockIdx.x * blockDim.x + threadIdx.x;
    if (e >= NET) return;
    int s, d;
    if (e < NE) { s = adj[e]; d = adj[NE + e]; }
    else        { s = e - NE; d = s; }
    int pos = atomicAdd(&g_cursor[d], 1);
    g_csr[pos] = s;
}

// ---------------- layer-1 softmax-aggregate + bias + ELU (warp per dst, MLP-4) ----------------
__global__ void agg1_k(const float* __restrict__ b1) {
    int n = (blockIdx.x * blockDim.x + threadIdx.x) >> 5;
    int lane = threadIdx.x & 31;
    if (n >= NN) return;
    int beg = g_row[n], end = g_row[n + 1];
    float4 adv = *(const float4*)&g_ad1[n * 4];

    float m[4] = {-1e30f, -1e30f, -1e30f, -1e30f};
    float s[4] = {0.f, 0.f, 0.f, 0.f};
    for (int e = beg + lane; e < end; e += 32) {
        int src = g_csr[e];
        float4 asv = *(const float4*)&g_as1[src * 4];
        float a[4] = {lrelu(asv.x + adv.x), lrelu(asv.y + adv.y),
                      lrelu(asv.z + adv.z), lrelu(asv.w + adv.w)};
        #pragma unroll
        for (int h = 0; h < 4; h++) {
            float mn = fmaxf(m[h], a[h]);
            s[h] = s[h] * expf(m[h] - mn) + expf(a[h] - mn);
            m[h] = mn;
        }
    }
    #pragma unroll
    for (int h = 0; h < 4; h++) {
        #pragma unroll
        for (int o = 16; o; o >>= 1) {
            float om = __shfl_xor_sync(0xFFFFFFFFu, m[h], o);
            float os = __shfl_xor_sync(0xFFFFFFFFu, s[h], o);
            float mn = fmaxf(m[h], om);
            s[h] = s[h] * expf(m[h] - mn) + os * expf(om - mn);
            m[h] = mn;
        }
    }

    int hh = lane >> 3;
    float myM = m[0], myS = s[0];
    if (hh == 1) { myM = m[1]; myS = s[1]; }
    else if (hh == 2) { myM = m[2]; myS = s[2]; }
    else if (hh == 3) { myM = m[3]; myS = s[3]; }
    float myInv = 1.f / myS;
    float myAd  = (hh == 0) ? adv.x : (hh == 1) ? adv.y : (hh == 2) ? adv.z : adv.w;

    float a0 = 0.f, a1 = 0.f, a2 = 0.f, a3 = 0.f, a4 = 0.f, a5 = 0.f, a6 = 0.f, a7 = 0.f;
    const uint4* h1p = (const uint4*)g_h1h;
    int e = beg;
    for (; e + 4 <= end; e += 4) {
        int s0 = g_csr[e], s1 = g_csr[e + 1], s2 = g_csr[e + 2], s3 = g_csr[e + 3];
        float w0 = lrelu(g_as1[s0 * 4 + hh] + myAd);
        float w1 = lrelu(g_as1[s1 * 4 + hh] + myAd);
        float w2 = lrelu(g_as1[s2 * 4 + hh] + myAd);
        float w3 = lrelu(g_as1[s3 * 4 + hh] + myAd);
        uint4 r0 = h1p[(size_t)s0 * 32 + lane];
        uint4 r1 = h1p[(size_t)s1 * 32 + lane];
        uint4 r2 = h1p[(size_t)s2 * 32 + lane];
        uint4 r3 = h1p[(size_t)s3 * 32 + lane];
        w0 = expf(w0 - myM) * myInv;
        w1 = expf(w1 - myM) * myInv;
        w2 = expf(w2 - myM) * myInv;
        w3 = expf(w3 - myM) * myInv;
        #pragma unroll
        for (int q = 0; q < 4; q++) {
            uint4 rr = (q == 0) ? r0 : (q == 1) ? r1 : (q == 2) ? r2 : r3;
            float ww = (q == 0) ? w0 : (q == 1) ? w1 : (q == 2) ? w2 : w3;
            float2 p0 = __half22float2(*(__half2*)&rr.x);
            float2 p1 = __half22float2(*(__half2*)&rr.y);
            float2 p2 = __half22float2(*(__half2*)&rr.z);
            float2 p3 = __half22float2(*(__half2*)&rr.w);
            a0 += ww * p0.x; a1 += ww * p0.y; a2 += ww * p1.x; a3 += ww * p1.y;
            a4 += ww * p2.x; a5 += ww * p2.y; a6 += ww * p3.x; a7 += ww * p3.y;
        }
    }
    for (; e < end; e++) {
        int src = g_csr[e];
        float w = expf(lrelu(g_as1[src * 4 + hh] + myAd) - myM) * myInv;
        uint4 raw = h1p[(size_t)src * 32 + lane];
        float2 p0 = __half22float2(*(__half2*)&raw.x);
        float2 p1 = __half22float2(*(__half2*)&raw.y);
        float2 p2 = __half22float2(*(__half2*)&raw.z);
        float2 p3 = __half22float2(*(__half2*)&raw.w);
        a0 += w * p0.x; a1 += w * p0.y; a2 += w * p1.x; a3 += w * p1.y;
        a4 += w * p2.x; a5 += w * p2.y; a6 += w * p3.x; a7 += w * p3.y;
    }
    int c0 = lane * 8;
    float4 bb0 = *(const float4*)&b1[c0];
    float4 bb1 = *(const float4*)&b1[c0 + 4];
    float o[8] = {a0 + bb0.x, a1 + bb0.y, a2 + bb0.z, a3 + bb0.w,
                  a4 + bb1.x, a5 + bb1.y, a6 + bb1.z, a7 + bb1.w};
    #pragma unroll
    for (int j = 0; j < 8; j++) o[j] = (o[j] > 0.f) ? o[j] : expm1f(o[j]);
    uint4 packed;
    *(__half2*)&packed.x = __float22half2_rn(make_float2(o[0], o[1]));
    *(__half2*)&packed.y = __float22half2_rn(make_float2(o[2], o[3]));
    *(__half2*)&packed.z = __float22half2_rn(make_float2(o[4], o[5]));
    *(__half2*)&packed.w = __float22half2_rn(make_float2(o[6], o[7]));
    *(uint4*)&g_heluh[(size_t)n * HHID + c0] = packed;
}

// ---------------- layer-2 softmax-aggregate + bias + log_softmax (MLP-4) ----------------
__global__ void agg2_k(const float* __restrict__ b2, float* __restrict__ out) {
    int n = (blockIdx.x * blockDim.x + threadIdx.x) >> 5;
    int lane = threadIdx.x & 31;
    if (n >= NN) return;
    int beg = g_row[n], end = g_row[n + 1];
    float adv = g_ad2[n];

    float m = -1e30f, ss = 0.f;
    for (int e = beg + lane; e < end; e += 32) {
        float a = lrelu(g_as2[g_csr[e]] + adv);
        float mn = fmaxf(m, a);
        ss = ss * expf(m - mn) + expf(a - mn);
        m = mn;
    }
    #pragma unroll
    for (int o = 16; o; o >>= 1) {
        float om = __shfl_xor_sync(0xFFFFFFFFu, m, o);
        float os = __shfl_xor_sync(0xFFFFFFFFu, ss, o);
        float mn = fmaxf(m, om);
        ss = ss * expf(m - mn) + os * expf(om - mn);
        m = mn;
    }
    float inv = 1.f / ss;

    float acc0 = 0.f, acc1 = 0.f;
    const __half2* h2p = (const __half2*)g_h2h;
    int e = beg;
    for (; e + 4 <= end; e += 4) {
        int s0 = g_csr[e], s1 = g_csr[e + 1], s2 = g_csr[e + 2], s3 = g_csr[e + 3];
        float w0 = lrelu(g_as2[s0] + adv);
        float w1 = lrelu(g_as2[s1] + adv);
        float w2 = lrelu(g_as2[s2] + adv);
        float w3 = lrelu(g_as2[s3] + adv);
        float2 v0 = __half22float2(h2p[(size_t)s0 * 32 + lane]);
        float2 v1 = __half22float2(h2p[(size_t)s1 * 32 + lane]);
        float2 v2 = __half22float2(h2p[(size_t)s2 * 32 + lane]);
        float2 v3 = __half22float2(h2p[(size_t)s3 * 32 + lane]);
        w0 = expf(w0 - m) * inv; w1 = expf(w1 - m) * inv;
        w2 = expf(w2 - m) * inv; w3 = expf(w3 - m) * inv;
        acc0 += w0 * v0.x + w1 * v1.x + w2 * v2.x + w3 * v3.x;
        acc1 += w0 * v0.y + w1 * v1.y + w2 * v2.y + w3 * v3.y;
    }
    for (; e < end; e++) {
        int src = g_csr[e];
        float w = expf(lrelu(g_as2[src] + adv) - m) * inv;
        float2 v = __half22float2(h2p[(size_t)src * 32 + lane]);
        acc0 += w * v.x; acc1 += w * v.y;
    }
    acc0 += b2[lane * 2]; acc1 += b2[lane * 2 + 1];

    float M = warpMax(fmaxf(acc0, acc1));
    float S = warpSum(expf(acc0 - M) + expf(acc1 - M));
    float L = M + logf(S);
    out[(size_t)n * OUTC + lane * 2]     = acc0 - L;
    out[(size_t)n * OUTC + lane * 2 + 1] = acc1 - L;
}

// ---------------- launch ----------------
extern "C" void kernel_launch(void* const* d_in, const int* in_sizes, int n_in,
                              void* d_out, int out_size) {
    const float* x        = (const float*)d_in[0];
    const int*   adj      = (const int*)d_in[1];
    const float* W1       = (const float*)d_in[2];
    const float* att_src1 = (const float*)d_in[3];
    const float* att_dst1 = (const float*)d_in[4];
    const float* b1       = (const float*)d_in[5];
    const float* W2       = (const float*)d_in[6];
    const float* att_src2 = (const float*)d_in[7];
    const float* att_dst2 = (const float*)d_in[8];
    const float* b2       = (const float*)d_in[9];
    float* out = (float*)d_out;

    __half *p_w1t, *p_w2t, *p_h1h, *p_heluh, *p_h2h;
    float *p_as1, *p_ad1, *p_as2, *p_ad2;
    int *p_deg;
    cudaGetSymbolAddress((void**)&p_w1t, g_w1t);
    cudaGetSymbolAddress((void**)&p_w2t, g_w2t);
    cudaGetSymbolAddress((void**)&p_h1h, g_h1h);
    cudaGetSymbolAddress((void**)&p_heluh, g_heluh);
    cudaGetSymbolAddress((void**)&p_h2h, g_h2h);
    cudaGetSymbolAddress((void**)&p_as1, g_as1);
    cudaGetSymbolAddress((void**)&p_ad1, g_ad1);
    cudaGetSymbolAddress((void**)&p_as2, g_as2);
    cudaGetSymbolAddress((void**)&p_ad2, g_ad2);
    cudaGetSymbolAddress((void**)&p_deg, g_deg);

    // one-time setup on the (uncaptured) correctness call
    static cudaStream_t s1 = nullptr;
    static cudaEvent_t evFork = nullptr, evJoin = nullptr;
    if (!s1) {
        cudaFuncSetAttribute(gemm_f32a_k, cudaFuncAttributeMaxDynamicSharedMemorySize, GEMM_SMEM_F);
        cudaFuncSetAttribute(gemm_h16_k, cudaFuncAttributeMaxDynamicSharedMemorySize, GEMM_SMEM_H);
        cudaStreamCreateWithFlags(&s1, cudaStreamNonBlocking);
        cudaEventCreateWithFlags(&evFork, cudaEventDisableTiming);
        cudaEventCreateWithFlags(&evJoin, cudaEventDisableTiming);
    }

    const int nodeBlocks = (NN * 32 + 255) / 256;
    const int edgeBlocks = (NET + 255) / 256;
    const int scanBlocks = (NN + 511) / 512;               // 98

    // fork: side stream runs weight-cvt + GEMM1 concurrent with CSR build
    cudaEventRecord(evFork, 0);
    cudaStreamWaitEvent(s1, evFork, 0);

    // main stream: CSR build chain
    cudaMemsetAsync(p_deg, 0, NN * sizeof(int), 0);
    count_k<<<edgeBlocks, 256>>>(adj);                                   // k1
    scan1_k<<<scanBlocks, 512>>>(NN);                                    // k2

    // side stream: cvtw + gemm1 (gemm1 = 4th issued kernel -> profiled)
    cvtw_k<<<20, 256, 0, s1>>>(W1, W2);                                  // k3
    gemm_f32a_k<<<dim3(HHID / TBN, (NN + TBM - 1) / TBM), 256, GEMM_SMEM_F, s1>>>(  // k4
        x, p_w1t, p_h1h, p_as1, p_ad1, att_src1, att_dst1, NH, NN, HHID, FIN);
    cudaEventRecord(evJoin, s1);

    scan2_k<<<1, 128>>>(scanBlocks);                                     // k5
    scan3_k<<<scanBlocks, 512>>>(NN);                                    // k6
    scatter_k<<<edgeBlocks, 256>>>(adj);                                 // k7

    // join: agg1 needs both gemm1 (h1h, as1/ad1) and CSR
    cudaStreamWaitEvent(0, evJoin, 0);
    agg1_k<<<nodeBlocks, 256>>>(b1);                                     // k8
    gemm_h16_k<<<dim3(OUTC / TBN, (NN + TBM - 1) / TBM), 256, GEMM_SMEM_H>>>(       // k9
        p_heluh, p_w2t, p_h2h, p_as2, p_ad2, att_src2, att_dst2, 1, NN, OUTC, HHID);
    agg2_k<<<nodeBlocks, 256>>>(b2, out);                                // k10
}

// round 8
// speedup vs baseline: 1.1085x; 1.0207x over previous
#include <cuda_runtime.h>
#include <cuda_fp16.h>
#include <math.h>

#define NN    50000
#define FIN   256
#define HHID  256
#define NH    4
#define HID   64
#define OUTC  64
#define NE    800000
#define NET   (NE + NN)
#define SLOPE 0.2f

// ---------------- device scratch ----------------
__device__ __half g_xh[NN * FIN];     // x fp16
__device__ __half g_w1t[HHID * FIN];  // W1^T [N][K] fp16
__device__ __half g_w2t[OUTC * HHID]; // W2^T [N][K] fp16
__device__ __half g_h1h[NN * HHID];
__device__ __half g_heluh[NN * HHID];
__device__ __half g_h2h[NN * OUTC];
__device__ float g_as1[NN * NH];
__device__ float g_ad1[NN * NH];
__device__ float g_as2[NN];
__device__ float g_ad2[NN];
__device__ __align__(16) int g_deg[NN];
__device__ __align__(16) int g_cursor[NN];
__device__ __align__(16) int g_row[NN + 4];
__device__ int g_csr[NET];
__device__ int g_bsums[128];

// ---------------- helpers ----------------
__device__ __forceinline__ float warpSum(float v) {
    #pragma unroll
    for (int o = 16; o; o >>= 1) v += __shfl_xor_sync(0xFFFFFFFFu, v, o);
    return v;
}
__device__ __forceinline__ float warpMax(float v) {
    #pragma unroll
    for (int o = 16; o; o >>= 1) v = fmaxf(v, __shfl_xor_sync(0xFFFFFFFFu, v, o));
    return v;
}
__device__ __forceinline__ float lrelu(float a) { return a > 0.f ? a : SLOPE * a; }

// ---------------- conversion kernels ----------------
__global__ void cvtx_k(const float* __restrict__ x) {
    int i = (blockIdx.x * 256 + threadIdx.x) * 4;
    float4 v = *(const float4*)&x[i];
    *(__half2*)&g_xh[i]     = __float22half2_rn(make_float2(v.x, v.y));
    *(__half2*)&g_xh[i + 2] = __float22half2_rn(make_float2(v.z, v.w));
}
__global__ void cvtw_k(const float* __restrict__ W1, const float* __restrict__ W2) {
    int b = blockIdx.x;
    if (b < 16) {
        int base = b * 4096 + threadIdx.x;
        #pragma unroll
        for (int it = 0; it < 16; it++) {
            int idx = base + it * 256;
            int k = idx >> 8, n = idx & 255;
            g_w1t[n * 256 + k] = __float2half(W1[idx]);
        }
    } else {
        int base = (b - 16) * 4096 + threadIdx.x;
        #pragma unroll
        for (int it = 0; it < 16; it++) {
            int idx = base + it * 256;
            int k = idx >> 6, n = idx & 63;
            g_w2t[n * 256 + k] = __float2half(W2[idx]);
        }
    }
}

// ---------------- fp16 GEMM, cp.async + ldmatrix, fused attention epilogue ----------------
#define TBM 128
#define TBN 64
#define TBK 64
#define AST 72
#define BST 72
#define GEMM_SMEM ((2 * TBM * AST + 2 * TBN * BST) * 2)

__device__ __forceinline__ void cp16(unsigned dst, const void* src, int sz) {
    asm volatile("cp.async.cg.shared.global [%0], [%1], 16, %2;\n"
                 :: "r"(dst), "l"(src), "r"(sz));
}
__device__ __forceinline__ void ldsm4(unsigned& r0, unsigned& r1, unsigned& r2, unsigned& r3,
                                      unsigned addr) {
    asm volatile("ldmatrix.sync.aligned.m8n8.x4.shared.b16 {%0,%1,%2,%3}, [%4];"
                 : "=r"(r0), "=r"(r1), "=r"(r2), "=r"(r3) : "r"(addr));
}
#define MMA_H16(accv, a0, a1, a2, a3, b0, b1)                                    \
    asm volatile("mma.sync.aligned.m16n8k16.row.col.f32.f16.f16.f32 "            \
                 "{%0,%1,%2,%3}, {%4,%5,%6,%7}, {%8,%9}, {%0,%1,%2,%3};"         \
                 : "+f"(accv[0]), "+f"(accv[1]), "+f"(accv[2]), "+f"(accv[3])    \
                 : "r"(a0), "r"(a1), "r"(a2), "r"(a3), "r"(b0), "r"(b1))

__global__ __launch_bounds__(256) void gemm_h16_k(
        const __half* __restrict__ A, const __half* __restrict__ Bt,
        __half* __restrict__ C,
        float* __restrict__ asOut, float* __restrict__ adOut,
        const float* __restrict__ attS, const float* __restrict__ attD,
        int asStr, int M, int Ncol, int K) {
    extern __shared__ char smem[];
    __half* As = (__half*)smem;
    __half* Bs = (__half*)smem + 2 * TBM * AST;
    const unsigned As_u = (unsigned)__cvta_generic_to_shared(As);
    const unsigned Bs_u = (unsigned)__cvta_generic_to_shared(Bs);

    const int tid = threadIdx.x;
    const int bm0 = blockIdx.y * TBM;
    const int bn0 = blockIdx.x * TBN;
    const int warpId = tid >> 5;
    const int lane = tid & 31;
    const int g  = lane >> 2;
    const int tg = lane & 3;
    const int wm = (warpId & 3) * 32;
    const int wn = (warpId >> 2) * 32;

    // ldmatrix per-lane selectors
    const int aRow = lane & 15;             // row within 16-row fragment
    const int aCol = (lane >> 4) * 8;       // 0 or 8
    const int bRowP = ((lane >> 4) * 8) + (lane & 7); // row within 16-row (2 nt) group
    const int bCol = ((lane >> 3) & 1) * 8;

    float acc[2][4][4];
    #pragma unroll
    for (int i = 0; i < 2; i++)
        #pragma unroll
        for (int j = 0; j < 4; j++)
            #pragma unroll
            for (int r = 0; r < 4; r++) acc[i][j][r] = 0.f;

    const int KT = K / TBK;

    auto loadTile = [&](int kt, int buf) {
        int k0 = kt * TBK;
        unsigned aBase = As_u + (unsigned)buf * TBM * AST * 2;
        unsigned bBase = Bs_u + (unsigned)buf * TBN * BST * 2;
        #pragma unroll
        for (int it = 0; it < 4; it++) {
            int idx = tid + it * 256;
            int m = idx >> 3, ch = idx & 7;
            const __half* src = A + (size_t)(bm0 + m) * K + k0 + ch * 8;
            int sz = (bm0 + m < M) ? 16 : 0;
            cp16(aBase + (unsigned)(m * AST + ch * 8) * 2, src, sz);
        }
        #pragma unroll
        for (int it = 0; it < 2; it++) {
            int idx = tid + it * 256;
            int n = idx >> 3, ch = idx & 7;
            const __half* src = Bt + (size_t)(bn0 + n) * K + k0 + ch * 8;
            cp16(bBase + (unsigned)(n * BST + ch * 8) * 2, src, 16);
        }
        asm volatile("cp.async.commit_group;\n");
    };

    loadTile(0, 0);

    for (int kt = 0; kt < KT; kt++) {
        if (kt + 1 < KT) {
            loadTile(kt + 1, (kt + 1) & 1);
            asm volatile("cp.async.wait_group 1;\n");
        } else {
            asm volatile("cp.async.wait_group 0;\n");
        }
        __syncthreads();

        unsigned AbU = As_u + (unsigned)(kt & 1) * TBM * AST * 2;
        unsigned BbU = Bs_u + (unsigned)(kt & 1) * TBN * BST * 2;

        #pragma unroll
        for (int kc = 0; kc < TBK; kc += 16) {
            unsigned af[2][4], bf[4][2];
            #pragma unroll
            for (int mt = 0; mt < 2; mt++) {
                unsigned addr = AbU + (unsigned)((wm + mt * 16 + aRow) * AST + kc + aCol) * 2;
                ldsm4(af[mt][0], af[mt][1], af[mt][2], af[mt][3], addr);
            }
            #pragma unroll
            for (int p = 0; p < 2; p++) {
                unsigned addr = BbU + (unsigned)((wn + p * 16 + bRowP) * BST + kc + bCol) * 2;
                ldsm4(bf[2 * p][0], bf[2 * p][1], bf[2 * p + 1][0], bf[2 * p + 1][1], addr);
            }
            #pragma unroll
            for (int mt = 0; mt < 2; mt++)
                #pragma unroll
                for (int nt = 0; nt < 4; nt++)
                    MMA_H16(acc[mt][nt], af[mt][0], af[mt][1], af[mt][2], af[mt][3],
                            bf[nt][0], bf[nt][1]);
        }
        __syncthreads();
    }

    // ---- epilogue: C store + fused attention dots ----
    #pragma unroll
    for (int mt = 0; mt < 2; mt++) {
        int r0 = bm0 + wm + mt * 16 + g;
        #pragma unroll
        for (int nt = 0; nt < 4; nt++) {
            int c = bn0 + wn + nt * 8 + tg * 2;
            if (r0 < M)
                *(__half2*)&C[(size_t)r0 * Ncol + c] =
                    __float22half2_rn(make_float2(acc[mt][nt][0], acc[mt][nt][1]));
            if (r0 + 8 < M)
                *(__half2*)&C[(size_t)(r0 + 8) * Ncol + c] =
                    __float22half2_rn(make_float2(acc[mt][nt][2], acc[mt][nt][3]));
        }
    }
    const float* aSp = attS + blockIdx.x * 64;
    const float* aDp = attD + blockIdx.x * 64;
    float pS[2][2] = {{0.f, 0.f}, {0.f, 0.f}};
    float pD[2][2] = {{0.f, 0.f}, {0.f, 0.f}};
    #pragma unroll
    for (int mt = 0; mt < 2; mt++)
        #pragma unroll
        for (int nt = 0; nt < 4; nt++) {
            int cIH = wn + nt * 8 + tg * 2;
            float s0 = aSp[cIH], s1 = aSp[cIH + 1];
            float d0 = aDp[cIH], d1 = aDp[cIH + 1];
            pS[mt][0] += acc[mt][nt][0] * s0 + acc[mt][nt][1] * s1;
            pS[mt][1] += acc[mt][nt][2] * s0 + acc[mt][nt][3] * s1;
            pD[mt][0] += acc[mt][nt][0] * d0 + acc[mt][nt][1] * d1;
            pD[mt][1] += acc[mt][nt][2] * d0 + acc[mt][nt][3] * d1;
        }
    #pragma unroll
    for (int o = 1; o <= 2; o <<= 1) {
        #pragma unroll
        for (int mt = 0; mt < 2; mt++)
            #pragma unroll
            for (int h = 0; h < 2; h++) {
                pS[mt][h] += __shfl_xor_sync(0xFFFFFFFFu, pS[mt][h], o);
                pD[mt][h] += __shfl_xor_sync(0xFFFFFFFFu, pD[mt][h], o);
            }
    }
    float* fbuf = (float*)smem;
    __syncthreads();
    if (tg == 0) {
        int warpN = warpId >> 2;
        #pragma unroll
        for (int mt = 0; mt < 2; mt++)
            #pragma unroll
            for (int h = 0; h < 2; h++) {
                int row = wm + mt * 16 + h * 8 + g;
                fbuf[(warpN * 128 + row) * 2 + 0] = pS[mt][h];
                fbuf[(warpN * 128 + row) * 2 + 1] = pD[mt][h];
            }
    }
    __syncthreads();
    if (tid < 128) {
        int gr = bm0 + tid;
        if (gr < M) {
            asOut[(size_t)gr * asStr + blockIdx.x] = fbuf[tid * 2] + fbuf[(128 + tid) * 2];
            adOut[(size_t)gr * asStr + blockIdx.x] = fbuf[tid * 2 + 1] + fbuf[(128 + tid) * 2 + 1];
        }
    }
}

// ---------------- CSR build ----------------
__global__ void count_k(const int* __restrict__ adj) {
    int e = blockIdx.x * blockDim.x + threadIdx.x;
    if (e >= NET) return;
    int d = (e < NE) ? adj[NE + e] : (e - NE);
    atomicAdd(&g_deg[d], 1);
}
__global__ void scan1_k(int n) {
    __shared__ int sh[512];
    int i = blockIdx.x * 512 + threadIdx.x;
    int v = (i < n) ? g_deg[i] : 0;
    sh[threadIdx.x] = v;
    __syncthreads();
    for (int off = 1; off < 512; off <<= 1) {
        int t = (threadIdx.x >= (unsigned)off) ? sh[threadIdx.x - off] : 0;
        __syncthreads();
        sh[threadIdx.x] += t;
        __syncthreads();
    }
    if (i < n) g_row[i] = sh[threadIdx.x] - v;
    if (threadIdx.x == 511) g_bsums[blockIdx.x] = sh[511];
}
__global__ void scan2_k(int nb) {
    __shared__ int sh[128];
    int v = (threadIdx.x < (unsigned)nb) ? g_bsums[threadIdx.x] : 0;
    sh[threadIdx.x] = v;
    __syncthreads();
    for (int off = 1; off < 128; off <<= 1) {
        int t = (threadIdx.x >= (unsigned)off) ? sh[threadIdx.x - off] : 0;
        __syncthreads();
        sh[threadIdx.x] += t;
        __syncthreads();
    }
    if (threadIdx.x < (unsigned)nb) g_bsums[threadIdx.x] = sh[threadIdx.x] - v;
}
__global__ void scan3_k(int n) {
    int i = blockIdx.x * 512 + threadIdx.x;
    if (i < n) {
        int r = g_row[i] + g_bsums[blockIdx.x];
        g_row[i] = r;
        g_cursor[i] = r;
    }
    if (i == 0) g_row[n] = NET;
}
__global__ void scatter_k(const int* __restrict__ adj) {
    int e = blockIdx.x * blockDim.x + threadIdx.x;
    if (e >= NET) return;
    int s, d;
    if (e < NE) { s = adj[e]; d = adj[NE + e]; }
    else        { s = e - NE; d = s; }
    int pos = atomicAdd(&g_cursor[d], 1);
    g_csr[pos] = s;
}

// ---------------- layer-1 softmax-aggregate + bias + ELU (warp per dst, MLP-4) ----------------
__global__ void agg1_k(const float* __restrict__ b1) {
    int n = (blockIdx.x * blockDim.x + threadIdx.x) >> 5;
    int lane = threadIdx.x & 31;
    if (n >= NN) return;
    int beg = g_row[n], end = g_row[n + 1];
    float4 adv = *(const float4*)&g_ad1[n * 4];

    float m[4] = {-1e30f, -1e30f, -1e30f, -1e30f};
    float s[4] = {0.f, 0.f, 0.f, 0.f};
    for (int e = beg + lane; e < end; e += 32) {
        int src = g_csr[e];
        float4 asv = *(const float4*)&g_as1[src * 4];
        float a[4] = {lrelu(asv.x + adv.x), lrelu(asv.y + adv.y),
                      lrelu(asv.z + adv.z), lrelu(asv.w + adv.w)};
        #pragma unroll
        for (int h = 0; h < 4; h++) {
            float mn = fmaxf(m[h], a[h]);
            s[h] = s[h] * expf(m[h] - mn) + expf(a[h] - mn);
            m[h] = mn;
        }
    }
    #pragma unroll
    for (int h = 0; h < 4; h++) {
        #pragma unroll
        for (int o = 16; o; o >>= 1) {
            float om = __shfl_xor_sync(0xFFFFFFFFu, m[h], o);
            float os = __shfl_xor_sync(0xFFFFFFFFu, s[h], o);
            float mn = fmaxf(m[h], om);
            s[h] = s[h] * expf(m[h] - mn) + os * expf(om - mn);
            m[h] = mn;
        }
    }

    int hh = lane >> 3;
    float myM = m[0], myS = s[0];
    if (hh == 1) { myM = m[1]; myS = s[1]; }
    else if (hh == 2) { myM = m[2]; myS = s[2]; }
    else if (hh == 3) { myM = m[3]; myS = s[3]; }
    float myInv = 1.f / myS;
    float myAd  = (hh == 0) ? adv.x : (hh == 1) ? adv.y : (hh == 2) ? adv.z : adv.w;

    float a0 = 0.f, a1 = 0.f, a2 = 0.f, a3 = 0.f, a4 = 0.f, a5 = 0.f, a6 = 0.f, a7 = 0.f;
    const uint4* h1p = (const uint4*)g_h1h;
    int e = beg;
    for (; e + 4 <= end; e += 4) {
        int s0 = g_csr[e], s1 = g_csr[e + 1], s2 = g_csr[e + 2], s3 = g_csr[e + 3];
        float w0 = lrelu(g_as1[s0 * 4 + hh] + myAd);
        float w1 = lrelu(g_as1[s1 * 4 + hh] + myAd);
        float w2 = lrelu(g_as1[s2 * 4 + hh] + myAd);
        float w3 = lrelu(g_as1[s3 * 4 + hh] + myAd);
        uint4 r0 = h1p[(size_t)s0 * 32 + lane];
        uint4 r1 = h1p[(size_t)s1 * 32 + lane];
        uint4 r2 = h1p[(size_t)s2 * 32 + lane];
        uint4 r3 = h1p[(size_t)s3 * 32 + lane];
        w0 = expf(w0 - myM) * myInv;
        w1 = expf(w1 - myM) * myInv;
        w2 = expf(w2 - myM) * myInv;
        w3 = expf(w3 - myM) * myInv;
        #pragma unroll
        for (int q = 0; q < 4; q++) {
            uint4 rr = (q == 0) ? r0 : (q == 1) ? r1 : (q == 2) ? r2 : r3;
            float ww = (q == 0) ? w0 : (q == 1) ? w1 : (q == 2) ? w2 : w3;
            float2 p0 = __half22float2(*(__half2*)&rr.x);
            float2 p1 = __half22float2(*(__half2*)&rr.y);
            float2 p2 = __half22float2(*(__half2*)&rr.z);
            float2 p3 = __half22float2(*(__half2*)&rr.w);
            a0 += ww * p0.x; a1 += ww * p0.y; a2 += ww * p1.x; a3 += ww * p1.y;
            a4 += ww * p2.x; a5 += ww * p2.y; a6 += ww * p3.x; a7 += ww * p3.y;
        }
    }
    for (; e < end; e++) {
        int src = g_csr[e];
        float w = expf(lrelu(g_as1[src * 4 + hh] + myAd) - myM) * myInv;
        uint4 raw = h1p[(size_t)src * 32 + lane];
        float2 p0 = __half22float2(*(__half2*)&raw.x);
        float2 p1 = __half22float2(*(__half2*)&raw.y);
        float2 p2 = __half22float2(*(__half2*)&raw.z);
        float2 p3 = __half22float2(*(__half2*)&raw.w);
        a0 += w * p0.x; a1 += w * p0.y; a2 += w * p1.x; a3 += w * p1.y;
        a4 += w * p2.x; a5 += w * p2.y; a6 += w * p3.x; a7 += w * p3.y;
    }
    int c0 = lane * 8;
    float4 bb0 = *(const float4*)&b1[c0];
    float4 bb1 = *(const float4*)&b1[c0 + 4];
    float o[8] = {a0 + bb0.x, a1 + bb0.y, a2 + bb0.z, a3 + bb0.w,
                  a4 + bb1.x, a5 + bb1.y, a6 + bb1.z, a7 + bb1.w};
    #pragma unroll
    for (int j = 0; j < 8; j++) o[j] = (o[j] > 0.f) ? o[j] : expm1f(o[j]);
    uint4 packed;
    *(__half2*)&packed.x = __float22half2_rn(make_float2(o[0], o[1]));
    *(__half2*)&packed.y = __float22half2_rn(make_float2(o[2], o[3]));
    *(__half2*)&packed.z = __float22half2_rn(make_float2(o[4], o[5]));
    *(__half2*)&packed.w = __float22half2_rn(make_float2(o[6], o[7]));
    *(uint4*)&g_heluh[(size_t)n * HHID + c0] = packed;
}

// ---------------- layer-2 softmax-aggregate + bias + log_softmax (MLP-4) ----------------
__global__ void agg2_k(const float* __restrict__ b2, float* __restrict__ out) {
    int n = (blockIdx.x * blockDim.x + threadIdx.x) >> 5;
    int lane = threadIdx.x & 31;
    if (n >= NN) return;
    int beg = g_row[n], end = g_row[n + 1];
    float adv = g_ad2[n];

    float m = -1e30f, ss = 0.f;
    for (int e = beg + lane; e < end; e += 32) {
        float a = lrelu(g_as2[g_csr[e]] + adv);
        float mn = fmaxf(m, a);
        ss = ss * expf(m - mn) + expf(a - mn);
        m = mn;
    }
    #pragma unroll
    for (int o = 16; o; o >>= 1) {
        float om = __shfl_xor_sync(0xFFFFFFFFu, m, o);
        float os = __shfl_xor_sync(0xFFFFFFFFu, ss, o);
        float mn = fmaxf(m, om);
        ss = ss * expf(m - mn) + os * expf(om - mn);
        m = mn;
    }
    float inv = 1.f / ss;

    float acc0 = 0.f, acc1 = 0.f;
    const __half2* h2p = (const __half2*)g_h2h;
    int e = beg;
    for (; e + 4 <= end; e += 4) {
        int s0 = g_csr[e], s1 = g_csr[e + 1], s2 = g_csr[e + 2], s3 = g_csr[e + 3];
        float w0 = lrelu(g_as2[s0] + adv);
        float w1 = lrelu(g_as2[s1] + adv);
        float w2 = lrelu(g_as2[s2] + adv);
        float w3 = lrelu(g_as2[s3] + adv);
        float2 v0 = __half22float2(h2p[(size_t)s0 * 32 + lane]);
        float2 v1 = __half22float2(h2p[(size_t)s1 * 32 + lane]);
        float2 v2 = __half22float2(h2p[(size_t)s2 * 32 + lane]);
        float2 v3 = __half22float2(h2p[(size_t)s3 * 32 + lane]);
        w0 = expf(w0 - m) * inv; w1 = expf(w1 - m) * inv;
        w2 = expf(w2 - m) * inv; w3 = expf(w3 - m) * inv;
        acc0 += w0 * v0.x + w1 * v1.x + w2 * v2.x + w3 * v3.x;
        acc1 += w0 * v0.y + w1 * v1.y + w2 * v2.y + w3 * v3.y;
    }
    for (; e < end; e++) {
        int src = g_csr[e];
        float w = expf(lrelu(g_as2[src] + adv) - m) * inv;
        float2 v = __half22float2(h2p[(size_t)src * 32 + lane]);
        acc0 += w * v.x; acc1 += w * v.y;
    }
    acc0 += b2[lane * 2]; acc1 += b2[lane * 2 + 1];

    float M = warpMax(fmaxf(acc0, acc1));
    float S = warpSum(expf(acc0 - M) + expf(acc1 - M));
    float L = M + logf(S);
    out[(size_t)n * OUTC + lane * 2]     = acc0 - L;
    out[(size_t)n * OUTC + lane * 2 + 1] = acc1 - L;
}

// ---------------- launch ----------------
extern "C" void kernel_launch(void* const* d_in, const int* in_sizes, int n_in,
                              void* d_out, int out_size) {
    const float* x        = (const float*)d_in[0];
    const int*   adj      = (const int*)d_in[1];
    const float* W1       = (const float*)d_in[2];
    const float* att_src1 = (const float*)d_in[3];
    const float* att_dst1 = (const float*)d_in[4];
    const float* b1       = (const float*)d_in[5];
    const float* W2       = (const float*)d_in[6];
    const float* att_src2 = (const float*)d_in[7];
    const float* att_dst2 = (const float*)d_in[8];
    const float* b2       = (const float*)d_in[9];
    float* out = (float*)d_out;

    __half *p_xh, *p_w1t, *p_w2t, *p_h1h, *p_heluh, *p_h2h;
    float *p_as1, *p_ad1, *p_as2, *p_ad2;
    int *p_deg;
    cudaGetSymbolAddress((void**)&p_xh, g_xh);
    cudaGetSymbolAddress((void**)&p_w1t, g_w1t);
    cudaGetSymbolAddress((void**)&p_w2t, g_w2t);
    cudaGetSymbolAddress((void**)&p_h1h, g_h1h);
    cudaGetSymbolAddress((void**)&p_heluh, g_heluh);
    cudaGetSymbolAddress((void**)&p_h2h, g_h2h);
    cudaGetSymbolAddress((void**)&p_as1, g_as1);
    cudaGetSymbolAddress((void**)&p_ad1, g_ad1);
    cudaGetSymbolAddress((void**)&p_as2, g_as2);
    cudaGetSymbolAddress((void**)&p_ad2, g_ad2);
    cudaGetSymbolAddress((void**)&p_deg, g_deg);

    static cudaStream_t s1 = nullptr;
    static cudaEvent_t evFork = nullptr, evJoin = nullptr;
    if (!s1) {
        cudaFuncSetAttribute(gemm_h16_k, cudaFuncAttributeMaxDynamicSharedMemorySize, GEMM_SMEM);
        cudaStreamCreateWithFlags(&s1, cudaStreamNonBlocking);
        cudaEventCreateWithFlags(&evFork, cudaEventDisableTiming);
        cudaEventCreateWithFlags(&evJoin, cudaEventDisableTiming);
    }

    const int nodeBlocks = (NN * 32 + 255) / 256;
    const int edgeBlocks = (NET + 255) / 256;
    const int scanBlocks = (NN + 511) / 512;

    // fork side stream
    cudaEventRecord(evFork, 0);
    cudaStreamWaitEvent(s1, evFork, 0);

    cudaMemsetAsync(p_deg, 0, NN * sizeof(int), 0);
    cvtx_k<<<NN * FIN / 1024, 256, 0, s1>>>(x);                          // k1 (side)
    count_k<<<edgeBlocks, 256>>>(adj);                                   // k2 (main)
    cvtw_k<<<20, 256, 0, s1>>>(W1, W2);                                  // k3 (side)
    gemm_h16_k<<<dim3(HHID / TBN, (NN + TBM - 1) / TBM), 256, GEMM_SMEM, s1>>>(  // k4 (profiled)
        p_xh, p_w1t, p_h1h, p_as1, p_ad1, att_src1, att_dst1, NH, NN, HHID, FIN);
    cudaEventRecord(evJoin, s1);

    scan1_k<<<scanBlocks, 512>>>(NN);                                    // k5
    scan2_k<<<1, 128>>>(scanBlocks);                                     // k6
    scan3_k<<<scanBlocks, 512>>>(NN);                                    // k7
    scatter_k<<<edgeBlocks, 256>>>(adj);                                 // k8

    cudaStreamWaitEvent(0, evJoin, 0);
    agg1_k<<<nodeBlocks, 256>>>(b1);                                     // k9
    gemm_h16_k<<<dim3(OUTC / TBN, (NN + TBM - 1) / TBM), 256, GEMM_SMEM>>>(      // k10
        p_heluh, p_w2t, p_h2h, p_as2, p_ad2, att_src2, att_dst2, 1, NN, OUTC, HHID);
    agg2_k<<<nodeBlocks, 256>>>(b2, out);                                // k11
}